// round 3
// baseline (speedup 1.0000x reference)
#include <cuda_runtime.h>

#define BB 2
#define NN 16384
#define KT 58
#define DD 64
#define ROWS (BB*NN)          // 32768
#define EDGES (BB*NN*KT)      // 1900544
#define NITER 10

// ---- scratch (static __device__ allocation — no runtime allocs) ----
__device__ float g_h[2][ROWS*DD];   // ping-pong h buffers (16 MB)
__device__ int   g_cnt[ROWS];       // in-degree counts
__device__ int   g_off[ROWS];       // CSR-T row starts (batch-local)
__device__ int   g_cur[ROWS];       // fill cursors; after fill == row ends
__device__ float g_w[EDGES];        // per-edge weight in (u,k) order
__device__ int2  g_edges[EDGES];    // CSR-T: {src u, weight bits}

__global__ void k_zero() {
    int i = blockIdx.x * blockDim.x + threadIdx.x;
    if (i < ROWS) g_cnt[i] = 0;
}

// h = softmax(h0) over D=64. One warp per row, lane handles d=lane, d=lane+32.
__global__ void k_softmax_h(const float* __restrict__ h0) {
    int wid  = (blockIdx.x * blockDim.x + threadIdx.x) >> 5;
    int lane = threadIdx.x & 31;
    if (wid >= ROWS) return;
    const float* r = h0 + (size_t)wid * DD;
    float a = r[lane], b = r[lane + 32];
    float m = fmaxf(a, b);
    #pragma unroll
    for (int o = 16; o; o >>= 1) m = fmaxf(m, __shfl_xor_sync(0xffffffffu, m, o));
    float ea = __expf(a - m), eb = __expf(b - m);
    float s = ea + eb;
    #pragma unroll
    for (int o = 16; o; o >>= 1) s += __shfl_xor_sync(0xffffffffu, s, o);
    float inv = 1.0f / s;
    float* w = g_h[0] + (size_t)wid * DD;
    w[lane]      = ea * inv;
    w[lane + 32] = eb * inv;
}

// adj weights: softmax/max(softmax) == exp(l - rowmax). Also count in-degrees.
__global__ void k_adj(const float* __restrict__ logits, const int* __restrict__ vind) {
    int wid  = (blockIdx.x * blockDim.x + threadIdx.x) >> 5;
    int lane = threadIdx.x & 31;
    if (wid >= ROWS) return;
    const float* r = logits + (size_t)wid * KT;
    float a = r[lane];
    float b = (lane < KT - 32) ? r[lane + 32] : -3.0e38f;
    float m = fmaxf(a, b);
    #pragma unroll
    for (int o = 16; o; o >>= 1) m = fmaxf(m, __shfl_xor_sync(0xffffffffu, m, o));
    int batch = wid / NN;
    const int* vr = vind + (size_t)wid * KT;
    {
        g_w[(size_t)wid * KT + lane] = __expf(a - m);
        int v = vr[lane];
        if ((unsigned)v < NN) atomicAdd(&g_cnt[batch * NN + v], 1);
    }
    if (lane < KT - 32) {
        g_w[(size_t)wid * KT + lane + 32] = __expf(b - m);
        int v = vr[lane + 32];
        if ((unsigned)v < NN) atomicAdd(&g_cnt[batch * NN + v], 1);
    }
}

// Exclusive scan of counts per batch. One block (1024 thr) per batch; 16 elems/thread.
__global__ void k_scan() {
    __shared__ int sh[1024];
    int b = blockIdx.x, t = threadIdx.x;
    const int per = NN / 1024;  // 16
    int base = b * NN + t * per;
    int loc[per];
    int s = 0;
    #pragma unroll
    for (int i = 0; i < per; i++) { loc[i] = s; s += g_cnt[base + i]; }
    sh[t] = s;
    __syncthreads();
    for (int o = 1; o < 1024; o <<= 1) {
        int add = (t >= o) ? sh[t - o] : 0;
        __syncthreads();
        sh[t] += add;
        __syncthreads();
    }
    int excl = sh[t] - s;
    #pragma unroll
    for (int i = 0; i < per; i++) {
        int o = excl + loc[i];
        g_off[base + i] = o;
        g_cur[base + i] = o;
    }
}

// Fill transposed CSR: one thread per edge (u,k) -> slot in destination v's list.
__global__ void k_fill(const int* __restrict__ vind) {
    int e = blockIdx.x * blockDim.x + threadIdx.x;
    if (e >= EDGES) return;
    int row   = e / KT;        // global source row in [0, B*N)
    int batch = row / NN;
    int u     = row % NN;
    int v = vind[e];
    if ((unsigned)v < NN) {
        int p = atomicAdd(&g_cur[batch * NN + v], 1);   // batch-local slot
        g_edges[(size_t)batch * NN * KT + p] = make_int2(u, __float_as_int(g_w[e]));
    }
}

// One propagation step: out[v] = L2norm( sum_e w_e * h[u_e] ). Warp per destination.
__global__ void k_prop(const float* __restrict__ hin, float* __restrict__ hout) {
    int wid  = (blockIdx.x * blockDim.x + threadIdx.x) >> 5;
    int lane = threadIdx.x & 31;
    if (wid >= ROWS) return;
    int batch = wid / NN;
    const float* hb = hin + (size_t)batch * NN * DD;
    const int2*  eb = g_edges + (size_t)batch * NN * KT;
    int beg = g_off[wid];
    int end = g_cur[wid];
    float acc0 = 0.0f, acc1 = 0.0f;
    int base = beg;
    int n = end - beg;
    while (n >= 32) {
        int2 ed = eb[base + lane];
        #pragma unroll
        for (int j = 0; j < 32; j++) {
            int   src = __shfl_sync(0xffffffffu, ed.x, j);
            float w   = __int_as_float(__shfl_sync(0xffffffffu, ed.y, j));
            const float* hr = hb + (size_t)src * DD;
            acc0 = fmaf(w, hr[lane],      acc0);
            acc1 = fmaf(w, hr[lane + 32], acc1);
        }
        base += 32;
        n -= 32;
    }
    if (n > 0) {
        int2 ed = (lane < n) ? eb[base + lane] : make_int2(0, 0);
        for (int j = 0; j < n; j++) {
            int   src = __shfl_sync(0xffffffffu, ed.x, j);
            float w   = __int_as_float(__shfl_sync(0xffffffffu, ed.y, j));
            const float* hr = hb + (size_t)src * DD;
            acc0 = fmaf(w, hr[lane],      acc0);
            acc1 = fmaf(w, hr[lane + 32], acc1);
        }
    }
    float ss = acc0 * acc0 + acc1 * acc1;
    #pragma unroll
    for (int o = 16; o; o >>= 1) ss += __shfl_xor_sync(0xffffffffu, ss, o);
    float scale = 1.0f / fmaxf(sqrtf(ss), 1e-12f);
    float* orow = hout + (size_t)wid * DD;
    orow[lane]      = acc0 * scale;
    orow[lane + 32] = acc1 * scale;
}

extern "C" void kernel_launch(void* const* d_in, const int* in_sizes, int n_in,
                              void* d_out, int out_size) {
    const float* logits = (const float*)d_in[0];
    const float* h0     = (const float*)d_in[1];
    const int*   vind   = (const int*)d_in[2];
    float*       out    = (float*)d_out;

    void* sym = nullptr;
    cudaGetSymbolAddress(&sym, g_h);
    float* buf0 = (float*)sym;
    float* buf1 = buf0 + (size_t)ROWS * DD;

    const int TPB = 256;
    const int warpBlocks = (ROWS * 32) / TPB;   // 4096 blocks, warp per row

    k_zero<<<(ROWS + TPB - 1) / TPB, TPB>>>();
    k_softmax_h<<<warpBlocks, TPB>>>(h0);
    k_adj<<<warpBlocks, TPB>>>(logits, vind);
    k_scan<<<BB, 1024>>>();
    k_fill<<<(EDGES + TPB - 1) / TPB, TPB>>>(vind);

    for (int it = 0; it < NITER; it++) {
        const float* in = (it & 1) ? buf1 : buf0;
        float* o = (it == NITER - 1) ? out : ((it & 1) ? buf0 : buf1);
        k_prop<<<warpBlocks, TPB>>>(in, o);
    }
}

// round 5
// speedup vs baseline: 1.2132x; 1.2132x over previous
#include <cuda_runtime.h>
#include <cuda_fp16.h>

#define BB 2
#define NN 16384
#define KT 58
#define DD 64
#define ROWS (BB*NN)          // 32768
#define NITER 10
#define STRIDE 160            // padded slots per destination row (P(overflow) ~ 1e-22)

// ---- static device scratch (no runtime allocs) ----
__device__ __half2  g_hh[2][ROWS * 32];        // ping-pong h, fp16, 4 MB each
__device__ int      g_cnt[ROWS];               // in-degree / fill cursor
__device__ unsigned g_edges[ROWS * STRIDE];    // packed {u:16 | half(w):16}, 21 MB

// h = softmax(h0) over D=64, stored fp16. Warp per row; lane owns dims {2L, 2L+1}.
// Also zeroes g_cnt for the fill pass.
__global__ void k_softmax_h(const float* __restrict__ h0) {
    int wid  = (blockIdx.x * blockDim.x + threadIdx.x) >> 5;
    int lane = threadIdx.x & 31;
    if (wid >= ROWS) return;
    if (lane == 0) g_cnt[wid] = 0;
    const float2* r = (const float2*)(h0 + (size_t)wid * DD);
    float2 v = r[lane];
    float m = fmaxf(v.x, v.y);
    #pragma unroll
    for (int o = 16; o; o >>= 1) m = fmaxf(m, __shfl_xor_sync(0xffffffffu, m, o));
    float ea = __expf(v.x - m), eb = __expf(v.y - m);
    float s = ea + eb;
    #pragma unroll
    for (int o = 16; o; o >>= 1) s += __shfl_xor_sync(0xffffffffu, s, o);
    float inv = 1.0f / s;
    g_hh[0][(size_t)wid * 32 + lane] = __floats2half2_rn(ea * inv, eb * inv);
}

// Fused adjacency + transposed fill: w = exp(l - rowmax) (== softmax/max(softmax)),
// slot p = atomicAdd(cnt[v]); write packed edge {u, half(w)} at v's padded row.
__global__ void k_adj_fill(const float* __restrict__ logits, const int* __restrict__ vind) {
    int wid  = (blockIdx.x * blockDim.x + threadIdx.x) >> 5;
    int lane = threadIdx.x & 31;
    if (wid >= ROWS) return;
    const float* r = logits + (size_t)wid * KT;
    float a = r[lane];
    float b = (lane < KT - 32) ? r[lane + 32] : -3.0e38f;
    float m = fmaxf(a, b);
    #pragma unroll
    for (int o = 16; o; o >>= 1) m = fmaxf(m, __shfl_xor_sync(0xffffffffu, m, o));
    int batch = wid / NN;
    int u     = wid - batch * NN;
    const int* vr = vind + (size_t)wid * KT;
    {
        int v = vr[lane];
        if ((unsigned)v < NN) {
            int gv = batch * NN + v;
            int p = atomicAdd(&g_cnt[gv], 1);
            unsigned hw = (unsigned)__half_as_ushort(__float2half_rn(__expf(a - m)));
            if (p < STRIDE) g_edges[(size_t)gv * STRIDE + p] = (unsigned)u | (hw << 16);
        }
    }
    if (lane < KT - 32) {
        int v = vr[lane + 32];
        if ((unsigned)v < NN) {
            int gv = batch * NN + v;
            int p = atomicAdd(&g_cnt[gv], 1);
            unsigned hw = (unsigned)__half_as_ushort(__float2half_rn(__expf(b - m)));
            if (p < STRIDE) g_edges[(size_t)gv * STRIDE + p] = (unsigned)u | (hw << 16);
        }
    }
}

// One propagation step: out[v] = L2norm( sum_e w_e * h[u_e] ).
// Warp per destination row; lane owns dims {2L, 2L+1} (one half2 = one 128B txn/edge).
// fout != nullptr on the last iteration -> write fp32 result.
__global__ void k_prop(const __half2* __restrict__ hin, __half2* __restrict__ hout,
                       float* __restrict__ fout) {
    int wid  = (blockIdx.x * blockDim.x + threadIdx.x) >> 5;
    int lane = threadIdx.x & 31;
    if (wid >= ROWS) return;
    int batch = wid / NN;
    const __half2*  hb = hin + (size_t)batch * NN * 32;
    const unsigned* eb = g_edges + (size_t)wid * STRIDE;
    int n = g_cnt[wid];
    if (n > STRIDE) n = STRIDE;
    float ax = 0.0f, ay = 0.0f;
    int base = 0;
    while (n >= 32) {
        unsigned ew = eb[base + lane];
        #pragma unroll
        for (int j = 0; j < 32; j++) {
            unsigned e = __shfl_sync(0xffffffffu, ew, j);
            int   src = (int)(e & 0xFFFFu);
            float w   = __half2float(__ushort_as_half((unsigned short)(e >> 16)));
            float2 hv = __half22float2(__ldg(hb + (size_t)src * 32 + lane));
            ax = fmaf(w, hv.x, ax);
            ay = fmaf(w, hv.y, ay);
        }
        base += 32;
        n -= 32;
    }
    if (n > 0) {
        unsigned ew = (lane < n) ? eb[base + lane] : 0u;
        for (int j = 0; j < n; j++) {
            unsigned e = __shfl_sync(0xffffffffu, ew, j);
            int   src = (int)(e & 0xFFFFu);
            float w   = __half2float(__ushort_as_half((unsigned short)(e >> 16)));
            float2 hv = __half22float2(__ldg(hb + (size_t)src * 32 + lane));
            ax = fmaf(w, hv.x, ax);
            ay = fmaf(w, hv.y, ay);
        }
    }
    float ss = ax * ax + ay * ay;
    #pragma unroll
    for (int o = 16; o; o >>= 1) ss += __shfl_xor_sync(0xffffffffu, ss, o);
    float scale = 1.0f / fmaxf(sqrtf(ss), 1e-12f);
    ax *= scale; ay *= scale;
    if (fout) {
        ((float2*)fout)[(size_t)wid * 32 + lane] = make_float2(ax, ay);
    } else {
        hout[(size_t)wid * 32 + lane] = __floats2half2_rn(ax, ay);
    }
}

extern "C" void kernel_launch(void* const* d_in, const int* in_sizes, int n_in,
                              void* d_out, int out_size) {
    const float* logits = (const float*)d_in[0];
    const float* h0     = (const float*)d_in[1];
    const int*   vind   = (const int*)d_in[2];
    float*       out    = (float*)d_out;

    void* sym = nullptr;
    cudaGetSymbolAddress(&sym, g_hh);
    __half2* buf0 = (__half2*)sym;
    __half2* buf1 = buf0 + (size_t)ROWS * 32;

    const int TPB = 256;
    const int warpBlocks = (ROWS * 32) / TPB;   // 4096 blocks, warp per row

    k_softmax_h<<<warpBlocks, TPB>>>(h0);
    k_adj_fill<<<warpBlocks, TPB>>>(logits, vind);

    for (int it = 0; it < NITER; it++) {
        const __half2* in = (it & 1) ? buf1 : buf0;
        __half2* o = (it & 1) ? buf0 : buf1;
        k_prop<<<warpBlocks, TPB>>>(in, o, (it == NITER - 1) ? out : nullptr);
    }
}

// round 8
// speedup vs baseline: 1.4623x; 1.2053x over previous
#include <cuda_runtime.h>
#include <cuda_fp16.h>

#define BB 2
#define NN 16384
#define KT 58
#define DD 64
#define ROWS (BB*NN)          // 32768
#define NITER 10
#define STRIDE 160            // padded slots per destination row (P(overflow) ~ 1e-22)

// ---- static device scratch (no runtime allocs) ----
__device__ __half2 g_hh[2][ROWS * 32];      // ping-pong h, fp16, 4 MB each
__device__ int     g_cnt[ROWS];             // in-degree / fill cursor
__device__ int2    g_edges[ROWS * STRIDE];  // pre-decoded {src, half2(w,w)}, 42 MB

static __device__ __forceinline__ unsigned h2_bits(__half2 h) {
    return *reinterpret_cast<unsigned*>(&h);
}

// h = softmax(h0) over D=64, stored fp16. Warp per row; lane owns dims {2L,2L+1}.
// Also zeroes g_cnt for the fill pass.
__global__ void k_softmax_h(const float* __restrict__ h0) {
    int wid  = (blockIdx.x * blockDim.x + threadIdx.x) >> 5;
    int lane = threadIdx.x & 31;
    if (wid >= ROWS) return;
    if (lane == 0) g_cnt[wid] = 0;
    const float2* r = (const float2*)(h0 + (size_t)wid * DD);
    float2 v = r[lane];
    float m = fmaxf(v.x, v.y);
    #pragma unroll
    for (int o = 16; o; o >>= 1) m = fmaxf(m, __shfl_xor_sync(0xffffffffu, m, o));
    float ea = __expf(v.x - m), eb = __expf(v.y - m);
    float s = ea + eb;
    #pragma unroll
    for (int o = 16; o; o >>= 1) s += __shfl_xor_sync(0xffffffffu, s, o);
    float inv = 1.0f / s;
    g_hh[0][(size_t)wid * 32 + lane] = __floats2half2_rn(ea * inv, eb * inv);
}

// Fused adjacency + transposed fill: w = exp(l - rowmax) (== softmax/max(softmax)).
// Slot p = atomicAdd(cnt[v]); write pre-decoded edge {u, half2(w,w)}.
__global__ void k_adj_fill(const float* __restrict__ logits, const int* __restrict__ vind) {
    int wid  = (blockIdx.x * blockDim.x + threadIdx.x) >> 5;
    int lane = threadIdx.x & 31;
    if (wid >= ROWS) return;
    const float* r = logits + (size_t)wid * KT;
    float a = r[lane];
    float b = (lane < KT - 32) ? r[lane + 32] : -3.0e38f;
    float m = fmaxf(a, b);
    #pragma unroll
    for (int o = 16; o; o >>= 1) m = fmaxf(m, __shfl_xor_sync(0xffffffffu, m, o));
    int batch = wid / NN;
    int u     = wid - batch * NN;
    const int* vr = vind + (size_t)wid * KT;
    {
        int v = vr[lane];
        if ((unsigned)v < NN) {
            int gv = batch * NN + v;
            int p = atomicAdd(&g_cnt[gv], 1);
            unsigned u16 = (unsigned)__half_as_ushort(__float2half_rn(__expf(a - m)));
            if (p < STRIDE)
                g_edges[(size_t)gv * STRIDE + p] = make_int2(u, (int)(u16 | (u16 << 16)));
        }
    }
    if (lane < KT - 32) {
        int v = vr[lane + 32];
        if ((unsigned)v < NN) {
            int gv = batch * NN + v;
            int p = atomicAdd(&g_cnt[gv], 1);
            unsigned u16 = (unsigned)__half_as_ushort(__float2half_rn(__expf(b - m)));
            if (p < STRIDE)
                g_edges[(size_t)gv * STRIDE + p] = make_int2(u, (int)(u16 | (u16 << 16)));
        }
    }
}

// One propagation step: out[v] = L2norm( sum_e w_e * h[u_e] ).
// Warp per destination row. 8 lanes per edge (octet o = lane>>3 handles edge q*4+o),
// lane covers 8 dims [(lane&7)*8 .. +8) via one 16B LDG.128 + 4 HFMA2.
// fp16 partials spilled to fp32 every <=4 quads (<=4 adds per partial) for precision.
__global__ void k_prop(const __half2* __restrict__ hin, __half2* __restrict__ hout,
                       float* __restrict__ fout) {
    int wid  = (blockIdx.x * blockDim.x + threadIdx.x) >> 5;
    int lane = threadIdx.x & 31;
    if (wid >= ROWS) return;
    int batch = wid / NN;
    int oct   = lane >> 3;     // which of 4 concurrent edges
    int chunk = lane & 7;      // which 16B slice of the 128B h row

    const char* hlane = (const char*)(hin + (size_t)batch * NN * 32) + chunk * 16;
    const int2* eb    = g_edges + (size_t)wid * STRIDE;

    int n = g_cnt[wid];
    if (n > STRIDE) n = STRIDE;
    int nq  = n >> 2;
    int rem = n & 3;

    float f0 = 0.f, f1 = 0.f, f2 = 0.f, f3 = 0.f, f4 = 0.f, f5 = 0.f, f6 = 0.f, f7 = 0.f;
    __half2 ha0 = __float2half2_rn(0.f), ha1 = ha0, ha2 = ha0, ha3 = ha0;

    int q = 0;
    // main: 4 quads (16 edges) per fp32 spill
    while (q + 4 <= nq) {
        #pragma unroll
        for (int k = 0; k < 4; k++) {
            int2 ed = eb[(q + k) * 4 + oct];
            __half2 ww = *reinterpret_cast<__half2*>(&ed.y);
            uint4 hv = *(const uint4*)(hlane + (size_t)ed.x * 128);
            ha0 = __hfma2(ww, *reinterpret_cast<__half2*>(&hv.x), ha0);
            ha1 = __hfma2(ww, *reinterpret_cast<__half2*>(&hv.y), ha1);
            ha2 = __hfma2(ww, *reinterpret_cast<__half2*>(&hv.z), ha2);
            ha3 = __hfma2(ww, *reinterpret_cast<__half2*>(&hv.w), ha3);
        }
        q += 4;
        { float2 t;
          t = __half22float2(ha0); f0 += t.x; f1 += t.y;
          t = __half22float2(ha1); f2 += t.x; f3 += t.y;
          t = __half22float2(ha2); f4 += t.x; f5 += t.y;
          t = __half22float2(ha3); f6 += t.x; f7 += t.y; }
        ha0 = ha1 = ha2 = ha3 = __float2half2_rn(0.f);
    }
    // leftover quads (<=3) + partial quad (<=3 edges): <=4 adds per partial, one spill
    for (; q < nq; q++) {
        int2 ed = eb[q * 4 + oct];
        __half2 ww = *reinterpret_cast<__half2*>(&ed.y);
        uint4 hv = *(const uint4*)(hlane + (size_t)ed.x * 128);
        ha0 = __hfma2(ww, *reinterpret_cast<__half2*>(&hv.x), ha0);
        ha1 = __hfma2(ww, *reinterpret_cast<__half2*>(&hv.y), ha1);
        ha2 = __hfma2(ww, *reinterpret_cast<__half2*>(&hv.z), ha2);
        ha3 = __hfma2(ww, *reinterpret_cast<__half2*>(&hv.w), ha3);
    }
    if (oct < rem) {
        int2 ed = eb[nq * 4 + oct];
        __half2 ww = *reinterpret_cast<__half2*>(&ed.y);
        uint4 hv = *(const uint4*)(hlane + (size_t)ed.x * 128);
        ha0 = __hfma2(ww, *reinterpret_cast<__half2*>(&hv.x), ha0);
        ha1 = __hfma2(ww, *reinterpret_cast<__half2*>(&hv.y), ha1);
        ha2 = __hfma2(ww, *reinterpret_cast<__half2*>(&hv.z), ha2);
        ha3 = __hfma2(ww, *reinterpret_cast<__half2*>(&hv.w), ha3);
    }
    { float2 t;
      t = __half22float2(ha0); f0 += t.x; f1 += t.y;
      t = __half22float2(ha1); f2 += t.x; f3 += t.y;
      t = __half22float2(ha2); f4 += t.x; f5 += t.y;
      t = __half22float2(ha3); f6 += t.x; f7 += t.y; }

    // merge the 4 edge-subsets (lanes chunk, chunk+8, chunk+16, chunk+24)
    #pragma unroll
    for (int o = 8; o <= 16; o <<= 1) {
        f0 += __shfl_xor_sync(0xffffffffu, f0, o);
        f1 += __shfl_xor_sync(0xffffffffu, f1, o);
        f2 += __shfl_xor_sync(0xffffffffu, f2, o);
        f3 += __shfl_xor_sync(0xffffffffu, f3, o);
        f4 += __shfl_xor_sync(0xffffffffu, f4, o);
        f5 += __shfl_xor_sync(0xffffffffu, f5, o);
        f6 += __shfl_xor_sync(0xffffffffu, f6, o);
        f7 += __shfl_xor_sync(0xffffffffu, f7, o);
    }
    // L2 norm: octet lanes 0..7 hold the 8 distinct dim-chunks
    float ss = f0*f0 + f1*f1 + f2*f2 + f3*f3 + f4*f4 + f5*f5 + f6*f6 + f7*f7;
    #pragma unroll
    for (int o = 1; o <= 4; o <<= 1) ss += __shfl_xor_sync(0xffffffffu, ss, o);
    float scale = 1.0f / fmaxf(sqrtf(ss), 1e-12f);
    f0 *= scale; f1 *= scale; f2 *= scale; f3 *= scale;
    f4 *= scale; f5 *= scale; f6 *= scale; f7 *= scale;

    if (lane < 8) {
        if (fout) {
            float4* orow = (float4*)(fout + (size_t)wid * DD);
            orow[chunk * 2]     = make_float4(f0, f1, f2, f3);
            orow[chunk * 2 + 1] = make_float4(f4, f5, f6, f7);
        } else {
            uint4 pk;
            pk.x = h2_bits(__floats2half2_rn(f0, f1));
            pk.y = h2_bits(__floats2half2_rn(f2, f3));
            pk.z = h2_bits(__floats2half2_rn(f4, f5));
            pk.w = h2_bits(__floats2half2_rn(f6, f7));
            ((uint4*)(hout + (size_t)wid * 32))[chunk] = pk;
        }
    }
}

extern "C" void kernel_launch(void* const* d_in, const int* in_sizes, int n_in,
                              void* d_out, int out_size) {
    const float* logits = (const float*)d_in[0];
    const float* h0     = (const float*)d_in[1];
    const int*   vind   = (const int*)d_in[2];
    float*       out    = (float*)d_out;

    void* sym = nullptr;
    cudaGetSymbolAddress(&sym, g_hh);
    __half2* buf0 = (__half2*)sym;
    __half2* buf1 = buf0 + (size_t)ROWS * 32;

    const int TPB = 256;
    const int warpBlocks = (ROWS * 32) / TPB;   // 4096 blocks, warp per row

    k_softmax_h<<<warpBlocks, TPB>>>(h0);
    k_adj_fill<<<warpBlocks, TPB>>>(logits, vind);

    for (int it = 0; it < NITER; it++) {
        const __half2* in = (it & 1) ? buf1 : buf0;
        __half2* o = (it & 1) ? buf0 : buf1;
        k_prop<<<warpBlocks, TPB>>>(in, o, (it == NITER - 1) ? out : nullptr);
    }
}

// round 9
// speedup vs baseline: 1.6624x; 1.1369x over previous
#include <cuda_runtime.h>
#include <cuda_fp16.h>

#define BB 2
#define NN 16384
#define KT 58
#define DD 64
#define ROWS (BB*NN)          // 32768
#define NITER 10
#define STRIDE 160            // padded slots per destination row (multiple of 16)

// ---- static device scratch (no runtime allocs) ----
__device__ __half2 g_hh[2][ROWS * 32];      // ping-pong h, fp16, 4 MB each
__device__ int     g_cnt[ROWS];             // in-degree / fill cursor (padded after k_pad)
__device__ int2    g_edges[ROWS * STRIDE];  // pre-decoded {src, half2(w,w)}, 42 MB

static __device__ __forceinline__ unsigned h2_bits(__half2 h) {
    return *reinterpret_cast<unsigned*>(&h);
}

// h = softmax(h0) over D=64, stored fp16. Warp per row; lane owns dims {2L,2L+1}.
// Also zeroes g_cnt for the fill pass.
__global__ void k_softmax_h(const float* __restrict__ h0) {
    int wid  = (blockIdx.x * blockDim.x + threadIdx.x) >> 5;
    int lane = threadIdx.x & 31;
    if (wid >= ROWS) return;
    if (lane == 0) g_cnt[wid] = 0;
    const float2* r = (const float2*)(h0 + (size_t)wid * DD);
    float2 v = r[lane];
    float m = fmaxf(v.x, v.y);
    #pragma unroll
    for (int o = 16; o; o >>= 1) m = fmaxf(m, __shfl_xor_sync(0xffffffffu, m, o));
    float ea = __expf(v.x - m), eb = __expf(v.y - m);
    float s = ea + eb;
    #pragma unroll
    for (int o = 16; o; o >>= 1) s += __shfl_xor_sync(0xffffffffu, s, o);
    float inv = 1.0f / s;
    g_hh[0][(size_t)wid * 32 + lane] = __floats2half2_rn(ea * inv, eb * inv);
}

// Fused adjacency + transposed fill: w = exp(l - rowmax) (== softmax/max(softmax)).
// Slot p = atomicAdd(cnt[v]); write pre-decoded edge {u, half2(w,w)}.
__global__ void k_adj_fill(const float* __restrict__ logits, const int* __restrict__ vind) {
    int wid  = (blockIdx.x * blockDim.x + threadIdx.x) >> 5;
    int lane = threadIdx.x & 31;
    if (wid >= ROWS) return;
    const float* r = logits + (size_t)wid * KT;
    float a = r[lane];
    float b = (lane < KT - 32) ? r[lane + 32] : -3.0e38f;
    float m = fmaxf(a, b);
    #pragma unroll
    for (int o = 16; o; o >>= 1) m = fmaxf(m, __shfl_xor_sync(0xffffffffu, m, o));
    int batch = wid / NN;
    int u     = wid - batch * NN;
    const int* vr = vind + (size_t)wid * KT;
    {
        int v = vr[lane];
        if ((unsigned)v < NN) {
            int gv = batch * NN + v;
            int p = atomicAdd(&g_cnt[gv], 1);
            unsigned u16 = (unsigned)__half_as_ushort(__float2half_rn(__expf(a - m)));
            if (p < STRIDE)
                g_edges[(size_t)gv * STRIDE + p] = make_int2(u, (int)(u16 | (u16 << 16)));
        }
    }
    if (lane < KT - 32) {
        int v = vr[lane + 32];
        if ((unsigned)v < NN) {
            int gv = batch * NN + v;
            int p = atomicAdd(&g_cnt[gv], 1);
            unsigned u16 = (unsigned)__half_as_ushort(__float2half_rn(__expf(b - m)));
            if (p < STRIDE)
                g_edges[(size_t)gv * STRIDE + p] = make_int2(u, (int)(u16 | (u16 << 16)));
        }
    }
}

// Pad each row's edge list to a multiple of 16 with zero-weight edges {src=0, w=0}
// so the prop kernel runs uniform 16-edge groups with no remainder handling.
__global__ void k_pad() {
    int i = blockIdx.x * blockDim.x + threadIdx.x;
    if (i >= ROWS) return;
    int c = g_cnt[i];
    if (c > STRIDE) c = STRIDE;
    int np = (c + 15) & ~15;            // STRIDE=160 is a multiple of 16 -> np <= STRIDE
    int2* e = g_edges + (size_t)i * STRIDE;
    for (int p = c; p < np; p++) e[p] = make_int2(0, 0);
    g_cnt[i] = np;
}

// One propagation step: out[v] = L2norm( sum_e w_e * h[u_e] ).
// Warp per destination row. 8 lanes per edge (octet = lane>>3), lane covers 8 dims
// [(lane&7)*8 .. +8) via one 16B LDG.128 + 4 HFMA2. Edge counts are padded to
// multiples of 16 -> uniform groups, fp32 spill once per 16-edge group.
template <bool LAST>
__global__ void __launch_bounds__(256, 6)
k_prop(const __half2* __restrict__ hin, __half2* __restrict__ hout,
       float* __restrict__ fout) {
    int wid  = (blockIdx.x * blockDim.x + threadIdx.x) >> 5;
    int lane = threadIdx.x & 31;
    if (wid >= ROWS) return;
    int batch = wid / NN;
    int oct   = lane >> 3;     // which of 4 concurrent edges
    int chunk = lane & 7;      // which 16B slice of the 128B h row

    const char* hlane = (const char*)(hin + (size_t)batch * NN * 32) + chunk * 16;
    const int2* eb    = g_edges + (size_t)wid * STRIDE + oct;

    int ng = g_cnt[wid] >> 4;  // number of 16-edge groups (uniform, no remainder)

    float f0 = 0.f, f1 = 0.f, f2 = 0.f, f3 = 0.f, f4 = 0.f, f5 = 0.f, f6 = 0.f, f7 = 0.f;

    for (int g = 0; g < ng; g++) {
        __half2 ha0 = __float2half2_rn(0.f), ha1 = ha0, ha2 = ha0, ha3 = ha0;
        #pragma unroll
        for (int k = 0; k < 4; k++) {
            int2 ed = eb[g * 16 + k * 4];
            __half2 ww = *reinterpret_cast<__half2*>(&ed.y);
            uint4 hv = *(const uint4*)(hlane + (size_t)ed.x * 128);
            ha0 = __hfma2(ww, *reinterpret_cast<__half2*>(&hv.x), ha0);
            ha1 = __hfma2(ww, *reinterpret_cast<__half2*>(&hv.y), ha1);
            ha2 = __hfma2(ww, *reinterpret_cast<__half2*>(&hv.z), ha2);
            ha3 = __hfma2(ww, *reinterpret_cast<__half2*>(&hv.w), ha3);
        }
        float2 t;
        t = __half22float2(ha0); f0 += t.x; f1 += t.y;
        t = __half22float2(ha1); f2 += t.x; f3 += t.y;
        t = __half22float2(ha2); f4 += t.x; f5 += t.y;
        t = __half22float2(ha3); f6 += t.x; f7 += t.y;
    }

    // merge the 4 edge-subsets (lanes chunk, chunk+8, chunk+16, chunk+24)
    #pragma unroll
    for (int o = 8; o <= 16; o <<= 1) {
        f0 += __shfl_xor_sync(0xffffffffu, f0, o);
        f1 += __shfl_xor_sync(0xffffffffu, f1, o);
        f2 += __shfl_xor_sync(0xffffffffu, f2, o);
        f3 += __shfl_xor_sync(0xffffffffu, f3, o);
        f4 += __shfl_xor_sync(0xffffffffu, f4, o);
        f5 += __shfl_xor_sync(0xffffffffu, f5, o);
        f6 += __shfl_xor_sync(0xffffffffu, f6, o);
        f7 += __shfl_xor_sync(0xffffffffu, f7, o);
    }
    // L2 norm: octet lanes 0..7 hold the 8 distinct dim-chunks
    float ss = f0*f0 + f1*f1 + f2*f2 + f3*f3 + f4*f4 + f5*f5 + f6*f6 + f7*f7;
    #pragma unroll
    for (int o = 1; o <= 4; o <<= 1) ss += __shfl_xor_sync(0xffffffffu, ss, o);
    float scale = 1.0f / fmaxf(sqrtf(ss), 1e-12f);
    f0 *= scale; f1 *= scale; f2 *= scale; f3 *= scale;
    f4 *= scale; f5 *= scale; f6 *= scale; f7 *= scale;

    if (lane < 8) {
        if (LAST) {
            float4* orow = (float4*)(fout + (size_t)wid * DD);
            orow[chunk * 2]     = make_float4(f0, f1, f2, f3);
            orow[chunk * 2 + 1] = make_float4(f4, f5, f6, f7);
        } else {
            uint4 pk;
            pk.x = h2_bits(__floats2half2_rn(f0, f1));
            pk.y = h2_bits(__floats2half2_rn(f2, f3));
            pk.z = h2_bits(__floats2half2_rn(f4, f5));
            pk.w = h2_bits(__floats2half2_rn(f6, f7));
            ((uint4*)(hout + (size_t)wid * 32))[chunk] = pk;
        }
    }
}

extern "C" void kernel_launch(void* const* d_in, const int* in_sizes, int n_in,
                              void* d_out, int out_size) {
    const float* logits = (const float*)d_in[0];
    const float* h0     = (const float*)d_in[1];
    const int*   vind   = (const int*)d_in[2];
    float*       out    = (float*)d_out;

    void* sym = nullptr;
    cudaGetSymbolAddress(&sym, g_hh);
    __half2* buf0 = (__half2*)sym;
    __half2* buf1 = buf0 + (size_t)ROWS * 32;

    const int TPB = 256;
    const int warpBlocks = (ROWS * 32) / TPB;   // 4096 blocks, warp per row

    k_softmax_h<<<warpBlocks, TPB>>>(h0);
    k_adj_fill<<<warpBlocks, TPB>>>(logits, vind);
    k_pad<<<(ROWS + TPB - 1) / TPB, TPB>>>();

    for (int it = 0; it < NITER; it++) {
        const __half2* in = (it & 1) ? buf1 : buf0;
        __half2* o = (it & 1) ? buf0 : buf1;
        if (it == NITER - 1)
            k_prop<true><<<warpBlocks, TPB>>>(in, o, out);
        else
            k_prop<false><<<warpBlocks, TPB>>>(in, o, nullptr);
    }
}

// round 11
// speedup vs baseline: 1.7061x; 1.0263x over previous
#include <cuda_runtime.h>
#include <cuda_fp16.h>

#define BB 2
#define NN 16384
#define KT 58
#define DD 64
#define ROWS (BB*NN)          // 32768
#define NITER 10
#define STRIDE 160            // padded slots per destination row (multiple of 16)

// ---- static device scratch (no runtime allocs) ----
__device__ __half2  g_hh[2][ROWS * 32];       // ping-pong h, fp16, 4 MB each
__device__ int      g_cnt[ROWS];              // in-degree / fill cursor (padded by k_pad)
__device__ unsigned g_edges[ROWS * STRIDE];   // packed {src:16 | fp16(w):16}, 21 MB

static __device__ __forceinline__ unsigned h2_bits(__half2 h) {
    return *reinterpret_cast<unsigned*>(&h);
}
// duplicate the high 16 bits (fp16 weight) into both halves -> half2(w, w)
static __device__ __forceinline__ __half2 dup_hi(unsigned e) {
    unsigned d;
    asm("prmt.b32 %0, %1, %1, 0x3232;" : "=r"(d) : "r"(e));
    return *reinterpret_cast<__half2*>(&d);
}

// h = softmax(h0) over D=64, stored fp16. Warp per row; lane owns dims {2L,2L+1}.
// Also zeroes g_cnt for the fill pass.
__global__ void k_softmax_h(const float* __restrict__ h0) {
    int wid  = (blockIdx.x * blockDim.x + threadIdx.x) >> 5;
    int lane = threadIdx.x & 31;
    if (wid >= ROWS) return;
    if (lane == 0) g_cnt[wid] = 0;
    const float2* r = (const float2*)(h0 + (size_t)wid * DD);
    float2 v = r[lane];
    float m = fmaxf(v.x, v.y);
    #pragma unroll
    for (int o = 16; o; o >>= 1) m = fmaxf(m, __shfl_xor_sync(0xffffffffu, m, o));
    float ea = __expf(v.x - m), eb = __expf(v.y - m);
    float s = ea + eb;
    #pragma unroll
    for (int o = 16; o; o >>= 1) s += __shfl_xor_sync(0xffffffffu, s, o);
    float inv = 1.0f / s;
    g_hh[0][(size_t)wid * 32 + lane] = __floats2half2_rn(ea * inv, eb * inv);
}

// Fused adjacency + transposed fill: w = exp(l - rowmax) (== softmax/max(softmax)).
// Slot p = atomicAdd(cnt[v]); write packed 4B edge {src:16 | half(w):16}.
__global__ void k_adj_fill(const float* __restrict__ logits, const int* __restrict__ vind) {
    int wid  = (blockIdx.x * blockDim.x + threadIdx.x) >> 5;
    int lane = threadIdx.x & 31;
    if (wid >= ROWS) return;
    const float* r = logits + (size_t)wid * KT;
    float a = r[lane];
    float b = (lane < KT - 32) ? r[lane + 32] : -3.0e38f;
    float m = fmaxf(a, b);
    #pragma unroll
    for (int o = 16; o; o >>= 1) m = fmaxf(m, __shfl_xor_sync(0xffffffffu, m, o));
    int batch = wid / NN;
    int u     = wid - batch * NN;
    const int* vr = vind + (size_t)wid * KT;
    {
        int v = vr[lane];
        if ((unsigned)v < NN) {
            int gv = batch * NN + v;
            int p = atomicAdd(&g_cnt[gv], 1);
            unsigned wb = (unsigned)__half_as_ushort(__float2half_rn(__expf(a - m)));
            if (p < STRIDE)
                g_edges[(size_t)gv * STRIDE + p] = (unsigned)u | (wb << 16);
        }
    }
    if (lane < KT - 32) {
        int v = vr[lane + 32];
        if ((unsigned)v < NN) {
            int gv = batch * NN + v;
            int p = atomicAdd(&g_cnt[gv], 1);
            unsigned wb = (unsigned)__half_as_ushort(__float2half_rn(__expf(b - m)));
            if (p < STRIDE)
                g_edges[(size_t)gv * STRIDE + p] = (unsigned)u | (wb << 16);
        }
    }
}

// Pad each row's edge list to a multiple of 4 with zero edges {src=0, w=0}.
// (avg padded degree ~60.5 vs ~66 when padding to 16 -> ~9% less gather traffic)
__global__ void k_pad() {
    int i = blockIdx.x * blockDim.x + threadIdx.x;
    if (i >= ROWS) return;
    int c = g_cnt[i];
    if (c > STRIDE) c = STRIDE;
    int np = (c + 3) & ~3;
    unsigned* e = g_edges + (size_t)i * STRIDE;
    for (int p = c; p < np; p++) e[p] = 0u;
    g_cnt[i] = np;
}

// One propagation step: out[v] = L2norm( sum_e w_e * h[u_e] ).
// Warp per destination row. 8 lanes per edge (octet = lane>>3 picks edge q*4+oct),
// lane covers 8 dims [(lane&7)*8..+8) via one 16B LDG.128 + 4 HFMA2.
// Main loop: 4 quads (16 edges) per fp32 spill; tail: <=3 quads, one spill.
template <bool LAST>
__global__ void __launch_bounds__(256, 6)
k_prop(const __half2* __restrict__ hin, __half2* __restrict__ hout,
       float* __restrict__ fout) {
    int wid  = (blockIdx.x * blockDim.x + threadIdx.x) >> 5;
    int lane = threadIdx.x & 31;
    if (wid >= ROWS) return;
    int batch = wid / NN;
    int oct   = lane >> 3;     // which of 4 concurrent edges in a quad
    int chunk = lane & 7;      // which 16B slice of the 128B h row

    const char*     hlane = (const char*)(hin + (size_t)batch * NN * 32) + chunk * 16;
    const unsigned* eb    = g_edges + (size_t)wid * STRIDE + oct;

    int nq  = g_cnt[wid] >> 2;     // quads (count is a multiple of 4)
    int nq4 = nq & ~3;             // full 16-edge super-groups

    float f0 = 0.f, f1 = 0.f, f2 = 0.f, f3 = 0.f, f4 = 0.f, f5 = 0.f, f6 = 0.f, f7 = 0.f;

    int q = 0;
    for (; q < nq4; q += 4) {
        __half2 ha0 = __float2half2_rn(0.f), ha1 = ha0, ha2 = ha0, ha3 = ha0;
        #pragma unroll
        for (int k = 0; k < 4; k++) {
            unsigned e = eb[(q + k) * 4];
            __half2 ww = dup_hi(e);
            uint4 hv = *(const uint4*)(hlane + (size_t)(e & 0xFFFFu) * 128);
            ha0 = __hfma2(ww, *reinterpret_cast<__half2*>(&hv.x), ha0);
            ha1 = __hfma2(ww, *reinterpret_cast<__half2*>(&hv.y), ha1);
            ha2 = __hfma2(ww, *reinterpret_cast<__half2*>(&hv.z), ha2);
            ha3 = __hfma2(ww, *reinterpret_cast<__half2*>(&hv.w), ha3);
        }
        float2 t;
        t = __half22float2(ha0); f0 += t.x; f1 += t.y;
        t = __half22float2(ha1); f2 += t.x; f3 += t.y;
        t = __half22float2(ha2); f4 += t.x; f5 += t.y;
        t = __half22float2(ha3); f6 += t.x; f7 += t.y;
    }
    if (q < nq) {                  // <=3 leftover quads: <=3 fp16 adds per partial
        __half2 ha0 = __float2half2_rn(0.f), ha1 = ha0, ha2 = ha0, ha3 = ha0;
        for (; q < nq; q++) {
            unsigned e = eb[q * 4];
            __half2 ww = dup_hi(e);
            uint4 hv = *(const uint4*)(hlane + (size_t)(e & 0xFFFFu) * 128);
            ha0 = __hfma2(ww, *reinterpret_cast<__half2*>(&hv.x), ha0);
            ha1 = __hfma2(ww, *reinterpret_cast<__half2*>(&hv.y), ha1);
            ha2 = __hfma2(ww, *reinterpret_cast<__half2*>(&hv.z), ha2);
            ha3 = __hfma2(ww, *reinterpret_cast<__half2*>(&hv.w), ha3);
        }
        float2 t;
        t = __half22float2(ha0); f0 += t.x; f1 += t.y;
        t = __half22float2(ha1); f2 += t.x; f3 += t.y;
        t = __half22float2(ha2); f4 += t.x; f5 += t.y;
        t = __half22float2(ha3); f6 += t.x; f7 += t.y;
    }

    // merge the 4 edge-subsets (lanes chunk, chunk+8, chunk+16, chunk+24)
    #pragma unroll
    for (int o = 8; o <= 16; o <<= 1) {
        f0 += __shfl_xor_sync(0xffffffffu, f0, o);
        f1 += __shfl_xor_sync(0xffffffffu, f1, o);
        f2 += __shfl_xor_sync(0xffffffffu, f2, o);
        f3 += __shfl_xor_sync(0xffffffffu, f3, o);
        f4 += __shfl_xor_sync(0xffffffffu, f4, o);
        f5 += __shfl_xor_sync(0xffffffffu, f5, o);
        f6 += __shfl_xor_sync(0xffffffffu, f6, o);
        f7 += __shfl_xor_sync(0xffffffffu, f7, o);
    }
    // L2 norm: octet lanes 0..7 hold the 8 distinct dim-chunks
    float ss = f0*f0 + f1*f1 + f2*f2 + f3*f3 + f4*f4 + f5*f5 + f6*f6 + f7*f7;
    #pragma unroll
    for (int o = 1; o <= 4; o <<= 1) ss += __shfl_xor_sync(0xffffffffu, ss, o);
    float scale = 1.0f / fmaxf(sqrtf(ss), 1e-12f);
    f0 *= scale; f1 *= scale; f2 *= scale; f3 *= scale;
    f4 *= scale; f5 *= scale; f6 *= scale; f7 *= scale;

    if (lane < 8) {
        if (LAST) {
            float4* orow = (float4*)(fout + (size_t)wid * DD);
            orow[chunk * 2]     = make_float4(f0, f1, f2, f3);
            orow[chunk * 2 + 1] = make_float4(f4, f5, f6, f7);
        } else {
            uint4 pk;
            pk.x = h2_bits(__floats2half2_rn(f0, f1));
            pk.y = h2_bits(__floats2half2_rn(f2, f3));
            pk.z = h2_bits(__floats2half2_rn(f4, f5));
            pk.w = h2_bits(__floats2half2_rn(f6, f7));
            ((uint4*)(hout + (size_t)wid * 32))[chunk] = pk;
        }
    }
}

extern "C" void kernel_launch(void* const* d_in, const int* in_sizes, int n_in,
                              void* d_out, int out_size) {
    const float* logits = (const float*)d_in[0];
    const float* h0     = (const float*)d_in[1];
    const int*   vind   = (const int*)d_in[2];
    float*       out    = (float*)d_out;

    void* sym = nullptr;
    cudaGetSymbolAddress(&sym, g_hh);
    __half2* buf0 = (__half2*)sym;
    __half2* buf1 = buf0 + (size_t)ROWS * 32;

    const int TPB = 256;
    const int warpBlocks = (ROWS * 32) / TPB;   // 4096 blocks, warp per row

    k_softmax_h<<<warpBlocks, TPB>>>(h0);
    k_adj_fill<<<warpBlocks, TPB>>>(logits, vind);
    k_pad<<<(ROWS + TPB - 1) / TPB, TPB>>>();

    for (int it = 0; it < NITER; it++) {
        const __half2* in = (it & 1) ? buf1 : buf0;
        __half2* o = (it & 1) ? buf0 : buf1;
        if (it == NITER - 1)
            k_prop<true><<<warpBlocks, TPB>>>(in, o, out);
        else
            k_prop<false><<<warpBlocks, TPB>>>(in, o, nullptr);
    }
}